// round 15
// baseline (speedup 1.0000x reference)
#include <cuda_runtime.h>
#include <cstdint>

// Shapes (fixed by the problem)
#define B 8
#define N 256
#define IN 64
#define F 64          // H*D
#define H 8
#define NPROD 128     // producer CTAs (K/V): 16 rows each
#define PPB 16        // producers per batch
#define NITEMS (B * N)   // 2048 work items (one row i each)
#define NCTA 592         // persistent grid: 4 CTAs x 148 SMs

#define L2E 1.4426950408889634f
#define M2C (20.0f * 1.4426950408889634f)   // fixed softmax shift (log2 domain)

typedef unsigned long long ull;

// ---- packed f32x2 helpers (sm_103a FFMA2/FADD2 only reachable via PTX) ----
__device__ __forceinline__ ull pack2(float lo, float hi) {
    ull r; asm("mov.b64 %0, {%1, %2};" : "=l"(r) : "f"(lo), "f"(hi)); return r;
}
__device__ __forceinline__ void unpack2(ull v, float& lo, float& hi) {
    asm("mov.b64 {%0, %1}, %2;" : "=f"(lo), "=f"(hi) : "l"(v));
}
__device__ __forceinline__ ull fma2(ull a, ull b, ull c) {
    ull d; asm("fma.rn.f32x2 %0, %1, %2, %3;" : "=l"(d) : "l"(a), "l"(b), "l"(c)); return d;
}
__device__ __forceinline__ ull add2(ull a, ull b) {
    ull d; asm("add.rn.f32x2 %0, %1, %2;" : "=l"(d) : "l"(a), "l"(b)); return d;
}
__device__ __forceinline__ float ex2(float x) {
    float y; asm("ex2.approx.ftz.f32 %0, %1;" : "=f"(y) : "f"(x)); return y;
}
// streaming 16B load (evict-first at L1+L2)
__device__ __forceinline__ ulonglong2 ldcs2(const ulonglong2* p) {
    ulonglong2 v;
    asm("ld.global.cs.v2.u64 {%0, %1}, [%2];" : "=l"(v.x), "=l"(v.y) : "l"(p));
    return v;
}
__device__ __forceinline__ void pf_l2(const void* p) {
    asm volatile("prefetch.global.L2 [%0];" :: "l"(p));
}

// Scratch (allocation-free rule: __device__ globals)
__device__ float g_K[B * N * F];   // pre-scaled by D^-0.5
__device__ float g_V[B * N * F];
__device__ int   g_done[B];        // per-batch producer counters
__device__ int   g_item = 0;       // work-stealing cursor
__device__ int   g_fin  = 0;       // CTAs finished (replay-safe reset)

// ---------------------------------------------------------------------------
// Persistent fused kernel. grid = 592 (4 CTAs/SM exactly), 256 threads.
// CTAs 0..127 first produce K/V for 16 rows each (batch = blk>>4).
// Then ALL CTAs steal items (one row i of one batch) via atomicAdd until
// the 2048 items are exhausted. Item: warp w owns j-slice [w*32, w*32+32);
// lanes jo = lane>>4 (j parity within step), q3 = lane&15 (float4 in f dim).
// Inner loop: f32x2 math, depth-2 ldcs pipeline on e_att/e_value, depth-1 V.
// ---------------------------------------------------------------------------
__global__ void __launch_bounds__(256, 4) fused_kernel(
    const float* __restrict__ h,
    const float* __restrict__ e_att,
    const float* __restrict__ e_value,
    const uint32_t* __restrict__ attn_mask,   // 4-byte elems; true <=> nonzero
    const float* __restrict__ Wq,
    const float* __restrict__ Wk,
    const float* __restrict__ Wv,
    float* __restrict__ out)
{
    __shared__ float qk_s[N][H];      // 8 KB; qk*L2E - M2, or -1e30 masked
    __shared__ float q_s[F];          // 256 B
    __shared__ float hrow_s[IN];      // 256 B
    __shared__ float msk_s[N];        // 1 KB
    __shared__ float part[8][32][9];  // 9 KB (padded); producers reuse as hs
    __shared__ int   s_item;

    const int blk  = blockIdx.x;
    const int tid  = threadIdx.x;
    const int wid  = tid >> 5;        // 0..7
    const int lane = tid & 31;

    // ================= producer: K/V projection (CTAs 0..127) ===============
    if (blk < NPROD) {
        float (*hs)[IN] = (float(*)[IN])&part[0][0][0];   // 16x64 = 4 KB, reused
        const int f    = tid & 63;
        const int rq   = tid >> 6;    // 0..3
        const int row0 = blk * 16;

        for (int t = tid; t < 16 * IN; t += 256)
            ((float*)hs)[t] = h[row0 * IN + t];
        __syncthreads();

        float ak[4] = {0, 0, 0, 0}, av[4] = {0, 0, 0, 0};
#pragma unroll 8
        for (int k = 0; k < IN; k++) {
            float wk = Wk[k * F + f];
            float wv = Wv[k * F + f];
#pragma unroll
            for (int rr = 0; rr < 4; rr++) {
                float hv = hs[rq + 4 * rr][k];
                ak[rr] = fmaf(hv, wk, ak[rr]);
                av[rr] = fmaf(hv, wv, av[rr]);
            }
        }
#pragma unroll
        for (int rr = 0; rr < 4; rr++) {
            int row = row0 + rq + 4 * rr;
            g_K[row * F + f] = ak[rr] * 0.35355339059327373f;  // D^-0.5
            g_V[row * F + f] = av[rr];
        }
        __threadfence();
        __syncthreads();
        if (tid == 0) atomicAdd(&g_done[blk >> 4], 1);
    }

    // phase-3 lane mapping (fixed per thread)
    const int jo = lane >> 4;         // 0/1
    const int q3 = lane & 15;         // float4 index in f dim
    const int j0 = wid * 32;          // this warp's j-slice

    // ======================= persistent work loop ==========================
    for (;;) {
        if (tid == 0) s_item = atomicAdd(&g_item, 1);
        __syncthreads();              // also the inter-item barrier
        const int item = s_item;
        if (item >= NITEMS) break;

        const int b = item >> 8;
        const int i = item & 255;

        const ulonglong2* pea = (const ulonglong2*)(e_att   + (size_t)(b * N + i) * N * F);
        const ulonglong2* pev = (const ulonglong2*)(e_value + (size_t)(b * N + i) * N * F);
        const int idx0   = (j0 + jo) * 16 + q3;
        const int idxmax = idx0 + 15 * 32;

        // L2 prefetch of the first steps (hides DRAM latency behind the front)
#pragma unroll
        for (int k = 0; k < 4; k++) {
            pf_l2(pea + idx0 + k * 32);
            pf_l2(pev + idx0 + k * 32);
        }

        // ---- front: mask row + h row + local Q ----
        msk_s[tid] = (attn_mask[(size_t)(b * N + i) * N + tid] != 0u) ? 1.0f : 0.0f;
        if (tid < IN) hrow_s[tid] = h[(b * N + i) * IN + tid];
        if (tid == 0) {
            while (*(volatile int*)&g_done[b] < PPB) __nanosleep(32);
        }
        __syncthreads();

        if (tid < F) {
            float acc = 0.f;
#pragma unroll 8
            for (int k = 0; k < IN; k++)
                acc = fmaf(hrow_s[k], Wq[k * F + tid], acc);
            q_s[tid] = acc;
        }
        __syncthreads();
        __threadfence();              // order g_K/g_V reads after flag

        // ---- phase 1 (warp-local j-slice): qk_s[j][h] ----
        {
            const int hh = lane >> 2; // 0..7
            const int jm = lane & 3;  // 0..3
            float qreg[8];
#pragma unroll
            for (int d = 0; d < 8; d++) qreg[d] = q_s[hh * 8 + d];

            const float4* Kb = (const float4*)(g_K + b * N * F);
#pragma unroll
            for (int jg = 0; jg < 8; jg++) {
                int j = j0 + jm + 4 * jg;
                float4 k0 = Kb[j * 16 + hh * 2];
                float4 k1 = Kb[j * 16 + hh * 2 + 1];
                float s = qreg[0] * k0.x;
                s = fmaf(qreg[1], k0.y, s);
                s = fmaf(qreg[2], k0.z, s);
                s = fmaf(qreg[3], k0.w, s);
                s = fmaf(qreg[4], k1.x, s);
                s = fmaf(qreg[5], k1.y, s);
                s = fmaf(qreg[6], k1.z, s);
                s = fmaf(qreg[7], k1.w, s);
                qk_s[j][hh] = (msk_s[j] != 0.0f) ? fmaf(s, L2E, -M2C)
                                                 : -1e30f;
            }
            __syncwarp();
        }

        // ---- phase 3: streaming softmax + weighted accumulation ----
        {
            const int hh = q3 >> 1;
            const ulonglong2* pV = (const ulonglong2*)(g_V + b * N * F);

            const ull L2E2 = pack2(L2E, L2E);
            ull L01 = 0ull, L23 = 0ull, A01 = 0ull, A23 = 0ull;

            ulonglong2 EA0 = ldcs2(pea + idx0),      EV0 = ldcs2(pev + idx0);
            ulonglong2 EA1 = ldcs2(pea + idx0 + 32), EV1 = ldcs2(pev + idx0 + 32);
            ulonglong2 VV0 = pV[idx0];

            int idx = idx0;
#pragma unroll 2
            for (int k = 0; k < 16; k++) {
                int idp2 = idx + 64;  idp2 = (idp2 <= idxmax) ? idp2 : idxmax;
                int idp1 = idx + 32;  idp1 = (idp1 <= idxmax) ? idp1 : idxmax;
                ulonglong2 EA2 = ldcs2(pea + idp2);
                ulonglong2 EV2 = ldcs2(pev + idp2);
                ulonglong2 VV1 = pV[idp1];

                float qk  = qk_s[j0 + 2 * k + jo][hh];
                ull   qk2 = pack2(qk, qk);

                ull t01 = fma2(EA0.x, L2E2, qk2);
                ull t23 = fma2(EA0.y, L2E2, qk2);
                float f0, f1, f2, f3;
                unpack2(t01, f0, f1);
                unpack2(t23, f2, f3);
                float p0 = ex2(f0), p1 = ex2(f1), p2 = ex2(f2), p3 = ex2(f3);
                ull p01 = pack2(p0, p1);
                ull p23 = pack2(p2, p3);

                L01 = add2(L01, p01);
                L23 = add2(L23, p23);
                ull w01 = add2(VV0.x, EV0.x);
                ull w23 = add2(VV0.y, EV0.y);
                A01 = fma2(p01, w01, A01);
                A23 = fma2(p23, w23, A23);

                EA0 = EA1; EV0 = EV1;
                EA1 = EA2; EV1 = EV2;
                VV0 = VV1;
                idx = idp1;
            }

            float l0, l1, l2, l3, a0, a1, a2, a3;
            unpack2(L01, l0, l1);
            unpack2(L23, l2, l3);
            unpack2(A01, a0, a1);
            unpack2(A23, a2, a3);

            part[wid][lane][0] = l0;
            part[wid][lane][1] = l1;
            part[wid][lane][2] = l2;
            part[wid][lane][3] = l3;
            part[wid][lane][4] = a0;
            part[wid][lane][5] = a1;
            part[wid][lane][6] = a2;
            part[wid][lane][7] = a3;
        }
        __syncthreads();

        // ---- combine 16 partials per f4 and write the row ----
        if (wid == 0 && lane < 16) {
            const int q = lane;
            float L[4] = {0, 0, 0, 0}, A[4] = {0, 0, 0, 0};
#pragma unroll
            for (int ww = 0; ww < 8; ww++) {
#pragma unroll
                for (int c = 0; c < 4; c++) {
                    L[c] += part[ww][q][c]     + part[ww][16 + q][c];
                    A[c] += part[ww][q][4 + c] + part[ww][16 + q][4 + c];
                }
            }
            float4 o;
            o.x = (L[0] > 0.f) ? A[0] / L[0] : 0.f;
            o.y = (L[1] > 0.f) ? A[1] / L[1] : 0.f;
            o.z = (L[2] > 0.f) ? A[2] / L[2] : 0.f;
            o.w = (L[3] > 0.f) ? A[3] / L[3] : 0.f;
            ((float4*)(out + (size_t)(b * N + i) * F))[q] = o;
        }
        // loop-top __syncthreads orders this combine before next item's writes
    }

    // ---- replay-safe reset of flags (last CTA to finish) ----
    if (tid == 0) {
        int f = atomicAdd(&g_fin, 1);
        if (f == NCTA - 1) {
#pragma unroll
            for (int bb = 0; bb < B; bb++) g_done[bb] = 0;
            g_item = 0;
            g_fin  = 0;
            __threadfence();
        }
    }
}

// ---------------------------------------------------------------------------
extern "C" void kernel_launch(void* const* d_in, const int* in_sizes, int n_in,
                              void* d_out, int out_size)
{
    const float*    h       = (const float*)d_in[0];
    const float*    e_att   = (const float*)d_in[1];
    const float*    e_value = (const float*)d_in[2];
    const uint32_t* mask    = (const uint32_t*)d_in[3];
    const float*    Wq      = (const float*)d_in[4];
    const float*    Wk      = (const float*)d_in[5];
    const float*    Wv      = (const float*)d_in[6];
    float*          out     = (float*)d_out;

    fused_kernel<<<NCTA, 256>>>(h, e_att, e_value, mask, Wq, Wk, Wv, out);
}